// round 1
// baseline (speedup 1.0000x reference)
#include <cuda_runtime.h>
#include <cstdint>

#define N_Q  8192
#define DIM  384
#define N_DOC 1024

// ---------------- scratch (static device globals; no allocation) -------------
__device__ float g_Q[(size_t)N_Q * DIM];      // normalized queries   12.6 MB
__device__ float g_C[(size_t)N_DOC * DIM];    // per-doc weighted sum  1.5 MB
__device__ float g_den[N_DOC];
__device__ float g_G[(size_t)N_Q * N_DOC];    // G = Q * C'^T         33.5 MB

// ---------------- f32x2 packed helpers ---------------------------------------
typedef unsigned long long u64;
__device__ __forceinline__ u64 pack2(float lo, float hi) {
    u64 r; asm("mov.b64 %0, {%1, %2};" : "=l"(r) : "f"(lo), "f"(hi)); return r;
}
__device__ __forceinline__ u64 fma2(u64 a, u64 b, u64 c) {
    u64 r; asm("fma.rn.f32x2 %0, %1, %2, %3;" : "=l"(r) : "l"(a), "l"(b), "l"(c)); return r;
}
__device__ __forceinline__ float2 unpack2(u64 v) {
    float2 f; asm("mov.b64 {%0, %1}, %2;" : "=f"(f.x), "=f"(f.y) : "l"(v)); return f;
}

// ---------------- kernel 0: zero the segment accumulators --------------------
__global__ void k_zero() {
    int idx = blockIdx.x * 256 + threadIdx.x;
    if (idx < N_DOC * DIM) g_C[idx] = 0.0f;
    if (idx < N_DOC)       g_den[idx] = 0.0f;
}

// ---------------- kernel 1: normalize rows + segment accumulate --------------
// one block (128 threads) per query row
__global__ __launch_bounds__(128) void k_norm_acc(
    const float* __restrict__ emb, const float* __restrict__ label,
    const int* __restrict__ did)
{
    int i = blockIdx.x;
    int t = threadIdx.x;
    const float* row = emb + (size_t)i * DIM;
    float v0 = row[t], v1 = row[t + 128], v2 = row[t + 256];
    float ss = v0 * v0 + v1 * v1 + v2 * v2;
    #pragma unroll
    for (int o = 16; o > 0; o >>= 1) ss += __shfl_xor_sync(0xFFFFFFFFu, ss, o);
    __shared__ float sred[4];
    if ((t & 31) == 0) sred[t >> 5] = ss;
    __syncthreads();
    float inv = 1.0f / sqrtf(sred[0] + sred[1] + sred[2] + sred[3]);

    float q0 = v0 * inv, q1 = v1 * inv, q2 = v2 * inv;
    float* qrow = g_Q + (size_t)i * DIM;
    qrow[t] = q0; qrow[t + 128] = q1; qrow[t + 256] = q2;

    float w = label[i];
    int   j = did[i];
    float* crow = g_C + (size_t)j * DIM;
    atomicAdd(&crow[t],       w * q0);
    atomicAdd(&crow[t + 128], w * q1);
    atomicAdd(&crow[t + 256], w * q2);
    if (t == 0) atomicAdd(&g_den[j], w);
}

// ---------------- kernel 2: C' = C / den --------------------------------------
__global__ __launch_bounds__(128) void k_scale() {
    int j = blockIdx.x;
    float den = g_den[j];
    float inv = (den != 0.0f) ? (1.0f / den) : 0.0f;
    float* crow = g_C + (size_t)j * DIM;
    for (int d = threadIdx.x; d < DIM; d += 128) crow[d] *= inv;
}

// ---------------- kernel 3: G = Q * C'^T  (128x128 tiles, f32x2 FMA) ----------
// grid (64, 8), 256 threads, each thread 8x8 outputs
__global__ __launch_bounds__(256) void k_gemm() {
    __shared__ float sA[8][128];
    __shared__ float sB[8][128];

    int bx = blockIdx.x;          // row-tile over N_Q
    int by = blockIdx.y;          // col-tile over N_DOC
    int tid = threadIdx.x;
    int tx = tid & 15;            // 0..15  -> 8 cols
    int ty = tid >> 4;            // 0..15  -> 8 rows

    int lrow = tid >> 1;          // 0..127
    int lcol = (tid & 1) * 4;     // 0 or 4

    const float* Ab = g_Q + ((size_t)bx * 128 + lrow) * DIM + lcol;
    const float* Bb = g_C + ((size_t)by * 128 + lrow) * DIM + lcol;

    u64 acc[8][4];
    #pragma unroll
    for (int i = 0; i < 8; i++)
        #pragma unroll
        for (int j = 0; j < 4; j++) acc[i][j] = 0ull;

    for (int k0 = 0; k0 < DIM; k0 += 8) {
        float4 a4 = *(const float4*)(Ab + k0);
        float4 b4 = *(const float4*)(Bb + k0);
        sA[lcol + 0][lrow] = a4.x; sA[lcol + 1][lrow] = a4.y;
        sA[lcol + 2][lrow] = a4.z; sA[lcol + 3][lrow] = a4.w;
        sB[lcol + 0][lrow] = b4.x; sB[lcol + 1][lrow] = b4.y;
        sB[lcol + 2][lrow] = b4.z; sB[lcol + 3][lrow] = b4.w;
        __syncthreads();

        #pragma unroll
        for (int k = 0; k < 8; k++) {
            float4 a0 = *(const float4*)&sA[k][ty * 8];
            float4 a1 = *(const float4*)&sA[k][ty * 8 + 4];
            float4 b0 = *(const float4*)&sB[k][tx * 8];
            float4 b1 = *(const float4*)&sB[k][tx * 8 + 4];
            u64 bp[4] = { pack2(b0.x, b0.y), pack2(b0.z, b0.w),
                          pack2(b1.x, b1.y), pack2(b1.z, b1.w) };
            float a[8] = { a0.x, a0.y, a0.z, a0.w, a1.x, a1.y, a1.z, a1.w };
            #pragma unroll
            for (int i = 0; i < 8; i++) {
                u64 ad = pack2(a[i], a[i]);
                #pragma unroll
                for (int j = 0; j < 4; j++) acc[i][j] = fma2(ad, bp[j], acc[i][j]);
            }
        }
        __syncthreads();
    }

    int row0 = bx * 128 + ty * 8;
    int col0 = by * 128 + tx * 8;
    #pragma unroll
    for (int i = 0; i < 8; i++) {
        float2 v0 = unpack2(acc[i][0]), v1 = unpack2(acc[i][1]);
        float2 v2 = unpack2(acc[i][2]), v3 = unpack2(acc[i][3]);
        float4 w0 = make_float4(v0.x, v0.y, v1.x, v1.y);
        float4 w1 = make_float4(v2.x, v2.y, v3.x, v3.y);
        size_t base = (size_t)(row0 + i) * N_DOC + col0;
        *(float4*)(g_G + base)     = w0;
        *(float4*)(g_G + base + 4) = w1;
    }
}

// ---------------- kernel 4: theta[i,q] = G[i, did[q]] -------------------------
// 8 rows per block; doc_ids staged once in shared; gather from shared G row.
__global__ __launch_bounds__(256) void k_expand(const int* __restrict__ did,
                                                float* __restrict__ out)
{
    __shared__ int   sdid[N_Q];   // 32 KB
    __shared__ float sG[N_DOC];   //  4 KB
    int t = threadIdx.x;
    for (int q = t; q < N_Q; q += 256) sdid[q] = did[q];

    int i0 = blockIdx.x * 8;
    for (int r = 0; r < 8; ++r) {
        int i = i0 + r;
        __syncthreads();   // guards sdid (r==0) and sG reuse (r>0)
        for (int j = t; j < N_DOC; j += 256) sG[j] = g_G[(size_t)i * N_DOC + j];
        __syncthreads();

        float4* orow = (float4*)(out + (size_t)i * N_Q);
        const int4* sdid4 = (const int4*)sdid;
        #pragma unroll 4
        for (int q4 = t; q4 < N_Q / 4; q4 += 256) {
            int4 d4 = sdid4[q4];
            float4 v;
            v.x = sG[d4.x]; v.y = sG[d4.y]; v.z = sG[d4.z]; v.w = sG[d4.w];
            orow[q4] = v;
        }
    }
}

// ---------------- launch ------------------------------------------------------
extern "C" void kernel_launch(void* const* d_in, const int* in_sizes, int n_in,
                              void* d_out, int out_size)
{
    const float* emb   = (const float*)d_in[0];
    const float* label = (const float*)d_in[1];
    const int*   did   = (const int*)d_in[2];
    float*       out   = (float*)d_out;

    k_zero<<<(N_DOC * DIM + 255) / 256, 256>>>();
    k_norm_acc<<<N_Q, 128>>>(emb, label, did);
    k_scale<<<N_DOC, 128>>>();
    k_gemm<<<dim3(64, 8), 256>>>();
    k_expand<<<N_Q / 8, 256>>>(did, out);
}

// round 4
// speedup vs baseline: 1.5160x; 1.5160x over previous
#include <cuda_runtime.h>
#include <cuda_bf16.h>
#include <cstdint>

#define N_Q   8192
#define DIM   384
#define N_DOC 1024
#define KEFF  1152          // 3 * DIM (hi|hi|lo x hi|lo|hi split)

// ---------------- scratch (static device globals; no allocation) -------------
__device__ float          g_C[(size_t)N_DOC * DIM];
__device__ float          g_den[N_DOC];
__device__ __nv_bfloat16  g_A2[(size_t)N_Q  * KEFF];   // 18.9 MB
__device__ __nv_bfloat16  g_B2[(size_t)N_DOC * KEFF];  //  2.4 MB
__device__ float          g_G[(size_t)N_Q * N_DOC];    // 33.5 MB

// ---------------- helpers -----------------------------------------------------
__device__ __forceinline__ uint32_t smem_u32(const void* p) {
    uint32_t a;
    asm("{ .reg .u64 t; cvta.to.shared.u64 t, %1; cvt.u32.u64 %0, t; }" : "=r"(a) : "l"(p));
    return a;
}
__device__ __forceinline__ void bf_split(float x, __nv_bfloat16& h, __nv_bfloat16& l) {
    h = __float2bfloat16(x);
    l = __float2bfloat16(x - __bfloat162float(h));
}
__device__ __forceinline__ void cp16(uint32_t dst, const void* src) {
    asm volatile("cp.async.cg.shared.global [%0], [%1], 16;" :: "r"(dst), "l"(src));
}
__device__ __forceinline__ void cp_commit() { asm volatile("cp.async.commit_group;"); }
__device__ __forceinline__ void ldsm4(uint32_t& r0, uint32_t& r1, uint32_t& r2, uint32_t& r3,
                                      uint32_t addr) {
    asm volatile("ldmatrix.sync.aligned.m8n8.x4.shared.b16 {%0,%1,%2,%3}, [%4];"
                 : "=r"(r0), "=r"(r1), "=r"(r2), "=r"(r3) : "r"(addr));
}
__device__ __forceinline__ void mma16816(float* c, const uint32_t* a, const uint32_t* b) {
    asm volatile(
        "mma.sync.aligned.m16n8k16.row.col.f32.bf16.bf16.f32 "
        "{%0,%1,%2,%3}, {%4,%5,%6,%7}, {%8,%9}, {%0,%1,%2,%3};"
        : "+f"(c[0]), "+f"(c[1]), "+f"(c[2]), "+f"(c[3])
        : "r"(a[0]), "r"(a[1]), "r"(a[2]), "r"(a[3]), "r"(b[0]), "r"(b[1]));
}

// ---------------- kernel 0: zero the segment accumulators --------------------
__global__ void k_zero() {
    int idx = blockIdx.x * 256 + threadIdx.x;
    if (idx < N_DOC * DIM) g_C[idx] = 0.0f;
    if (idx < N_DOC)       g_den[idx] = 0.0f;
}

// ---------------- kernel 1: normalize + write A2(hi|hi|lo) + segment acc -----
__global__ __launch_bounds__(128) void k_norm_acc(
    const float* __restrict__ emb, const float* __restrict__ label,
    const int* __restrict__ did)
{
    int i = blockIdx.x;
    int t = threadIdx.x;
    const float* row = emb + (size_t)i * DIM;
    float v0 = row[t], v1 = row[t + 128], v2 = row[t + 256];
    float ss = v0 * v0 + v1 * v1 + v2 * v2;
    #pragma unroll
    for (int o = 16; o > 0; o >>= 1) ss += __shfl_xor_sync(0xFFFFFFFFu, ss, o);
    __shared__ float sred[4];
    if ((t & 31) == 0) sred[t >> 5] = ss;
    __syncthreads();
    float inv = rsqrtf(sred[0] + sred[1] + sred[2] + sred[3]);

    float q[3] = { v0 * inv, v1 * inv, v2 * inv };
    __nv_bfloat16* arow = g_A2 + (size_t)i * KEFF;
    #pragma unroll
    for (int s = 0; s < 3; ++s) {
        int d = t + s * 128;
        __nv_bfloat16 h, l;
        bf_split(q[s], h, l);
        arow[d]           = h;   // block 0: hi
        arow[d + DIM]     = h;   // block 1: hi
        arow[d + 2 * DIM] = l;   // block 2: lo
    }

    float w = label[i];
    int   j = did[i];
    float* crow = g_C + (size_t)j * DIM;
    atomicAdd(&crow[t],       w * q[0]);
    atomicAdd(&crow[t + 128], w * q[1]);
    atomicAdd(&crow[t + 256], w * q[2]);
    if (t == 0) atomicAdd(&g_den[j], w);
}

// ---------------- kernel 2: B2 = split(C/den) as (hi|lo|hi) -------------------
__global__ __launch_bounds__(128) void k_scale() {
    int j = blockIdx.x;
    float inv = 1.0f / g_den[j];
    const float* crow = g_C + (size_t)j * DIM;
    __nv_bfloat16* brow = g_B2 + (size_t)j * KEFF;
    for (int d = threadIdx.x; d < DIM; d += 128) {
        float y = crow[d] * inv;
        __nv_bfloat16 h, l;
        bf_split(y, h, l);
        brow[d]           = h;   // block 0: hi
        brow[d + DIM]     = l;   // block 1: lo
        brow[d + 2 * DIM] = h;   // block 2: hi
    }
}

// ---------------- kernel 3: HMMA GEMM  G = A2 * B2^T --------------------------
// 128x128 tile, BK=32, 8 warps (2m x 4n), m16n8k16 bf16, cp.async double buffer.
// Smem rows padded to 80B -> ldmatrix conflict-free.
#define BK        32
#define ROWB      80                    // 64B data + 16B pad
#define TILE_SB   (128 * ROWB)          // 10240 B
#define K_ITERS   (KEFF / BK)           // 36

__global__ __launch_bounds__(256, 2) void k_gemm() {
    __shared__ __align__(128) char sA[2][TILE_SB];
    __shared__ __align__(128) char sB[2][TILE_SB];

    int tid  = threadIdx.x;
    int lane = tid & 31;
    int wid  = tid >> 5;
    int warp_m = wid >> 2;           // 0..1  -> 64 rows
    int warp_n = wid & 3;            // 0..3  -> 32 cols
    int tm = blockIdx.x;             // 0..63
    int tn = blockIdx.y;             // 0..7

    const __nv_bfloat16* Abase = g_A2 + (size_t)(tm * 128) * KEFF;
    const __nv_bfloat16* Bbase = g_B2 + (size_t)(tn * 128) * KEFF;

    uint32_t sAu = smem_u32(sA), sBu = smem_u32(sB);

    // per-thread cp.async assignment: 512 chunks of 16B per tile, 2 per thread
    int r0c = tid >> 1;              // row 0..127
    int c0c = (tid & 1) * 2;         // chunk 0 or 2 (each thread does c, c+1)

    float acc[4][4][4];
    #pragma unroll
    for (int i = 0; i < 4; i++)
        #pragma unroll
        for (int j = 0; j < 4; j++)
            #pragma unroll
            for (int v = 0; v < 4; v++) acc[i][j][v] = 0.0f;

    // ---- prologue: load chunk 0 into buffer 0
    {
        const __nv_bfloat16* as = Abase + (size_t)r0c * KEFF;
        const __nv_bfloat16* bs = Bbase + (size_t)r0c * KEFF;
        uint32_t ad = sAu + r0c * ROWB;
        uint32_t bd = sBu + r0c * ROWB;
        cp16(ad + c0c * 16,        as + c0c * 8);
        cp16(ad + (c0c + 1) * 16,  as + (c0c + 1) * 8);
        cp16(bd + c0c * 16,        bs + c0c * 8);
        cp16(bd + (c0c + 1) * 16,  bs + (c0c + 1) * 8);
        cp_commit();
    }

    // ldmatrix lane addressing offsets
    int a_row = warp_m * 64 + (lane & 15);        // + mi*16
    int a_off = (lane >> 4) * 16;                 // k half within 32B
    int b_row = warp_n * 32 + ((lane >> 4) * 8 + (lane & 7));   // + nt2*16
    int b_off = ((lane >> 3) & 1) * 16;

    #pragma unroll 1
    for (int it = 0; it < K_ITERS; ++it) {
        int buf = it & 1;

        if (it + 1 < K_ITERS) {   // prefetch next chunk into other buffer
            int k0 = (it + 1) * BK;
            int nb = buf ^ 1;
            const __nv_bfloat16* as = Abase + (size_t)r0c * KEFF + k0;
            const __nv_bfloat16* bs = Bbase + (size_t)r0c * KEFF + k0;
            uint32_t ad = sAu + nb * TILE_SB + r0c * ROWB;
            uint32_t bd = sBu + nb * TILE_SB + r0c * ROWB;
            cp16(ad + c0c * 16,        as + c0c * 8);
            cp16(ad + (c0c + 1) * 16,  as + (c0c + 1) * 8);
            cp16(bd + c0c * 16,        bs + c0c * 8);
            cp16(bd + (c0c + 1) * 16,  bs + (c0c + 1) * 8);
            cp_commit();
            asm volatile("cp.async.wait_group 1;");
        } else {
            asm volatile("cp.async.wait_group 0;");
        }
        __syncthreads();

        uint32_t sab = sAu + buf * TILE_SB;
        uint32_t sbb = sBu + buf * TILE_SB;

        #pragma unroll
        for (int kk = 0; kk < 2; ++kk) {
            uint32_t a[4][4];
            #pragma unroll
            for (int mi = 0; mi < 4; ++mi)
                ldsm4(a[mi][0], a[mi][1], a[mi][2], a[mi][3],
                      sab + (a_row + mi * 16) * ROWB + kk * 32 + a_off);
            uint32_t b[4][2];
            #pragma unroll
            for (int nt2 = 0; nt2 < 2; ++nt2) {
                uint32_t r0, r1, r2, r3;
                ldsm4(r0, r1, r2, r3,
                      sbb + (b_row + nt2 * 16) * ROWB + kk * 32 + b_off);
                b[nt2 * 2][0] = r0;     b[nt2 * 2][1] = r1;
                b[nt2 * 2 + 1][0] = r2; b[nt2 * 2 + 1][1] = r3;
            }
            #pragma unroll
            for (int mi = 0; mi < 4; ++mi)
                #pragma unroll
                for (int nj = 0; nj < 4; ++nj)
                    mma16816(acc[mi][nj], a[mi], b[nj]);
        }
        __syncthreads();
    }

    // ---- epilogue: write 64x32 warp tile to g_G
    int rbase = tm * 128 + warp_m * 64 + (lane >> 2);
    int cbase = tn * 128 + warp_n * 32 + (lane & 3) * 2;
    #pragma unroll
    for (int mi = 0; mi < 4; ++mi) {
        #pragma unroll
        for (int nj = 0; nj < 4; ++nj) {
            int r = rbase + mi * 16;
            int c = cbase + nj * 8;
            *(float2*)(g_G + (size_t)r * N_DOC + c) =
                make_float2(acc[mi][nj][0], acc[mi][nj][1]);
            *(float2*)(g_G + (size_t)(r + 8) * N_DOC + c) =
                make_float2(acc[mi][nj][2], acc[mi][nj][3]);
        }
    }
}

// ---------------- kernel 4: theta[i,q] = G[i, did[q]] -------------------------
__global__ __launch_bounds__(256) void k_expand(const int* __restrict__ did,
                                                float* __restrict__ out)
{
    __shared__ int   sdid[N_Q];   // 32 KB
    __shared__ float sG[N_DOC];   //  4 KB
    int t = threadIdx.x;
    for (int q = t; q < N_Q; q += 256) sdid[q] = did[q];

    int i0 = blockIdx.x * 8;
    for (int r = 0; r < 8; ++r) {
        int i = i0 + r;
        __syncthreads();
        for (int j = t; j < N_DOC; j += 256) sG[j] = g_G[(size_t)i * N_DOC + j];
        __syncthreads();

        float4* orow = (float4*)(out + (size_t)i * N_Q);
        const int4* sdid4 = (const int4*)sdid;
        #pragma unroll 4
        for (int q4 = t; q4 < N_Q / 4; q4 += 256) {
            int4 d4 = sdid4[q4];
            float4 v;
            v.x = sG[d4.x]; v.y = sG[d4.y]; v.z = sG[d4.z]; v.w = sG[d4.w];
            orow[q4] = v;
        }
    }
}

// ---------------- launch ------------------------------------------------------
extern "C" void kernel_launch(void* const* d_in, const int* in_sizes, int n_in,
                              void* d_out, int out_size)
{
    const float* emb   = (const float*)d_in[0];
    const float* label = (const float*)d_in[1];
    const int*   did   = (const int*)d_in[2];
    float*       out   = (float*)d_out;

    k_zero<<<(N_DOC * DIM + 255) / 256, 256>>>();
    k_norm_acc<<<N_Q, 128>>>(emb, label, did);
    k_scale<<<N_DOC, 128>>>();
    k_gemm<<<dim3(64, 8), 256>>>();
    k_expand<<<N_Q / 8, 256>>>(did, out);
}

// round 5
// speedup vs baseline: 1.7196x; 1.1344x over previous
#include <cuda_runtime.h>
#include <cuda_bf16.h>
#include <cstdint>

#define N_Q   8192
#define DIM   384
#define N_DOC 1024
#define KEFF  1152          // 3 * DIM (hi|hi|lo x hi|lo|hi split)

// ---------------- scratch (static device globals; no allocation) -------------
__device__ float          g_C[(size_t)N_DOC * DIM];
__device__ float          g_den[N_DOC];
__device__ __nv_bfloat16  g_A2[(size_t)N_Q  * KEFF];   // 18.9 MB
__device__ __nv_bfloat16  g_B2[(size_t)N_DOC * KEFF];  //  2.4 MB
__device__ float          g_G[(size_t)N_Q * N_DOC];    // 33.5 MB

// ---------------- helpers -----------------------------------------------------
__device__ __forceinline__ uint32_t smem_u32(const void* p) {
    uint32_t a;
    asm("{ .reg .u64 t; cvta.to.shared.u64 t, %1; cvt.u32.u64 %0, t; }" : "=r"(a) : "l"(p));
    return a;
}
__device__ __forceinline__ void bf_split(float x, __nv_bfloat16& h, __nv_bfloat16& l) {
    h = __float2bfloat16(x);
    l = __float2bfloat16(x - __bfloat162float(h));
}
__device__ __forceinline__ void cp16(uint32_t dst, const void* src) {
    asm volatile("cp.async.cg.shared.global [%0], [%1], 16;" :: "r"(dst), "l"(src));
}
__device__ __forceinline__ void cp_commit() { asm volatile("cp.async.commit_group;"); }
__device__ __forceinline__ void ldsm4(uint32_t& r0, uint32_t& r1, uint32_t& r2, uint32_t& r3,
                                      uint32_t addr) {
    asm volatile("ldmatrix.sync.aligned.m8n8.x4.shared.b16 {%0,%1,%2,%3}, [%4];"
                 : "=r"(r0), "=r"(r1), "=r"(r2), "=r"(r3) : "r"(addr));
}
__device__ __forceinline__ void mma16816(float* c, const uint32_t* a, const uint32_t* b) {
    asm volatile(
        "mma.sync.aligned.m16n8k16.row.col.f32.bf16.bf16.f32 "
        "{%0,%1,%2,%3}, {%4,%5,%6,%7}, {%8,%9}, {%0,%1,%2,%3};"
        : "+f"(c[0]), "+f"(c[1]), "+f"(c[2]), "+f"(c[3])
        : "r"(a[0]), "r"(a[1]), "r"(a[2]), "r"(a[3]), "r"(b[0]), "r"(b[1]));
}

// ---------------- kernel 0: zero the segment accumulators --------------------
__global__ void k_zero() {
    int idx = blockIdx.x * 256 + threadIdx.x;
    if (idx < N_DOC * DIM) g_C[idx] = 0.0f;
    if (idx < N_DOC)       g_den[idx] = 0.0f;
}

// ---------------- kernel 1: normalize + write A2(hi|hi|lo) + segment acc -----
__global__ __launch_bounds__(128) void k_norm_acc(
    const float* __restrict__ emb, const float* __restrict__ label,
    const int* __restrict__ did)
{
    int i = blockIdx.x;
    int t = threadIdx.x;
    const float* row = emb + (size_t)i * DIM;
    float v0 = row[t], v1 = row[t + 128], v2 = row[t + 256];
    float ss = v0 * v0 + v1 * v1 + v2 * v2;
    #pragma unroll
    for (int o = 16; o > 0; o >>= 1) ss += __shfl_xor_sync(0xFFFFFFFFu, ss, o);
    __shared__ float sred[4];
    if ((t & 31) == 0) sred[t >> 5] = ss;
    __syncthreads();
    float inv = rsqrtf(sred[0] + sred[1] + sred[2] + sred[3]);

    float q[3] = { v0 * inv, v1 * inv, v2 * inv };
    __nv_bfloat16* arow = g_A2 + (size_t)i * KEFF;
    #pragma unroll
    for (int s = 0; s < 3; ++s) {
        int d = t + s * 128;
        __nv_bfloat16 h, l;
        bf_split(q[s], h, l);
        arow[d]           = h;   // block 0: hi
        arow[d + DIM]     = h;   // block 1: hi
        arow[d + 2 * DIM] = l;   // block 2: lo
    }

    float w = label[i];
    int   j = did[i];
    float* crow = g_C + (size_t)j * DIM;
    atomicAdd(&crow[t],       w * q[0]);
    atomicAdd(&crow[t + 128], w * q[1]);
    atomicAdd(&crow[t + 256], w * q[2]);
    if (t == 0) atomicAdd(&g_den[j], w);
}

// ---------------- kernel 2: B2 = split(C/den) as (hi|lo|hi) -------------------
__global__ __launch_bounds__(128) void k_scale() {
    int j = blockIdx.x;
    float inv = 1.0f / g_den[j];
    const float* crow = g_C + (size_t)j * DIM;
    __nv_bfloat16* brow = g_B2 + (size_t)j * KEFF;
    for (int d = threadIdx.x; d < DIM; d += 128) {
        float y = crow[d] * inv;
        __nv_bfloat16 h, l;
        bf_split(y, h, l);
        brow[d]           = h;   // block 0: hi
        brow[d + DIM]     = l;   // block 1: lo
        brow[d + 2 * DIM] = h;   // block 2: hi
    }
}

// ---------------- kernel 3: HMMA GEMM  G = A2 * B2^T --------------------------
// 128x128 tile, BK=64, 8 warps (2m x 4n), m16n8k16 bf16,
// 3-stage cp.async pipeline, one __syncthreads per K-chunk.
// Smem rows 144B (128B data + 16B pad): (r*144) % 128 = 16r % 128 -> the 8 rows
// of every ldmatrix hit 8 distinct 16B bank groups => conflict-free.
#define BK        64
#define ROWB      144
#define STAGE_SB  (128 * ROWB)          // 18432 B per matrix per stage
#define STAGES    3
#define K_ITERS   (KEFF / BK)           // 18
#define SM_TOTAL  (2 * STAGES * STAGE_SB)   // 110592 B

__global__ __launch_bounds__(256, 2) void k_gemm() {
    extern __shared__ __align__(128) char smem[];
    uint32_t sAu = smem_u32(smem);                       // 3 A stages
    uint32_t sBu = sAu + STAGES * STAGE_SB;              // 3 B stages

    int tid  = threadIdx.x;
    int lane = tid & 31;
    int wid  = tid >> 5;
    int warp_m = wid >> 2;           // 0..1  -> 64 rows
    int warp_n = wid & 3;            // 0..3  -> 32 cols
    int tm = blockIdx.x;             // 0..63
    int tn = blockIdx.y;             // 0..7

    const __nv_bfloat16* Abase = g_A2 + (size_t)(tm * 128) * KEFF;
    const __nv_bfloat16* Bbase = g_B2 + (size_t)(tn * 128) * KEFF;

    float acc[4][4][4];
    #pragma unroll
    for (int i = 0; i < 4; i++)
        #pragma unroll
        for (int j = 0; j < 4; j++)
            #pragma unroll
            for (int v = 0; v < 4; v++) acc[i][j][v] = 0.0f;

    // cp.async assignment: 1024 16B-chunks per matrix per stage, 4 per thread
    // idx = tid + j*256 ; r = idx>>3 (0..127), c = idx&7 (0..7)
    auto issue_stage = [&](int stage_k, int buf) {
        int k0 = stage_k * BK;
        uint32_t ad = sAu + buf * STAGE_SB;
        uint32_t bd = sBu + buf * STAGE_SB;
        #pragma unroll
        for (int j = 0; j < 4; ++j) {
            int idx = tid + j * 256;
            int r = idx >> 3, c = idx & 7;
            cp16(ad + r * ROWB + c * 16, Abase + (size_t)r * KEFF + k0 + c * 8);
            cp16(bd + r * ROWB + c * 16, Bbase + (size_t)r * KEFF + k0 + c * 8);
        }
        cp_commit();
    };

    // ---- prologue: stages 0 and 1 in flight
    issue_stage(0, 0);
    issue_stage(1, 1);

    // ldmatrix lane addressing offsets (same fragment math as the passing R4)
    int a_row = warp_m * 64 + (lane & 15);                      // + mi*16
    int a_off = (lane >> 4) * 16;                               // k half within 32B
    int b_row = warp_n * 32 + ((lane >> 4) * 8 + (lane & 7));   // + nt2*16
    int b_off = ((lane >> 3) & 1) * 16;

    #pragma unroll 1
    for (int it = 0; it < K_ITERS; ++it) {
        int buf = it % STAGES;

        asm volatile("cp.async.wait_group 1;");   // stage `it` has landed
        __syncthreads();                          // publish it; retire buf of it-1

        if (it + 2 < K_ITERS) issue_stage(it + 2, (it + 2) % STAGES);

        uint32_t sab = sAu + buf * STAGE_SB;
        uint32_t sbb = sBu + buf * STAGE_SB;

        #pragma unroll
        for (int kk = 0; kk < 4; ++kk) {
            uint32_t a[4][4];
            #pragma unroll
            for (int mi = 0; mi < 4; ++mi)
                ldsm4(a[mi][0], a[mi][1], a[mi][2], a[mi][3],
                      sab + (a_row + mi * 16) * ROWB + kk * 32 + a_off);
            uint32_t b[4][2];
            #pragma unroll
            for (int nt2 = 0; nt2 < 2; ++nt2) {
                uint32_t r0, r1, r2, r3;
                ldsm4(r0, r1, r2, r3,
                      sbb + (b_row + nt2 * 16) * ROWB + kk * 32 + b_off);
                b[nt2 * 2][0] = r0;     b[nt2 * 2][1] = r1;
                b[nt2 * 2 + 1][0] = r2; b[nt2 * 2 + 1][1] = r3;
            }
            #pragma unroll
            for (int mi = 0; mi < 4; ++mi)
                #pragma unroll
                for (int nj = 0; nj < 4; ++nj)
                    mma16816(acc[mi][nj], a[mi], b[nj]);
        }
    }

    // ---- epilogue: write 64x32 warp tile to g_G
    int rbase = tm * 128 + warp_m * 64 + (lane >> 2);
    int cbase = tn * 128 + warp_n * 32 + (lane & 3) * 2;
    #pragma unroll
    for (int mi = 0; mi < 4; ++mi) {
        #pragma unroll
        for (int nj = 0; nj < 4; ++nj) {
            int r = rbase + mi * 16;
            int c = cbase + nj * 8;
            *(float2*)(g_G + (size_t)r * N_DOC + c) =
                make_float2(acc[mi][nj][0], acc[mi][nj][1]);
            *(float2*)(g_G + (size_t)(r + 8) * N_DOC + c) =
                make_float2(acc[mi][nj][2], acc[mi][nj][3]);
        }
    }
}

// ---------------- kernel 4: theta[i,q] = G[i, did[q]] -------------------------
__global__ __launch_bounds__(256) void k_expand(const int* __restrict__ did,
                                                float* __restrict__ out)
{
    __shared__ int   sdid[N_Q];   // 32 KB
    __shared__ float sG[N_DOC];   //  4 KB
    int t = threadIdx.x;
    for (int q = t; q < N_Q; q += 256) sdid[q] = did[q];

    int i0 = blockIdx.x * 8;
    for (int r = 0; r < 8; ++r) {
        int i = i0 + r;
        __syncthreads();
        for (int j = t; j < N_DOC; j += 256) sG[j] = g_G[(size_t)i * N_DOC + j];
        __syncthreads();

        float4* orow = (float4*)(out + (size_t)i * N_Q);
        const int4* sdid4 = (const int4*)sdid;
        #pragma unroll 4
        for (int q4 = t; q4 < N_Q / 4; q4 += 256) {
            int4 d4 = sdid4[q4];
            float4 v;
            v.x = sG[d4.x]; v.y = sG[d4.y]; v.z = sG[d4.z]; v.w = sG[d4.w];
            orow[q4] = v;
        }
    }
}

// ---------------- launch ------------------------------------------------------
extern "C" void kernel_launch(void* const* d_in, const int* in_sizes, int n_in,
                              void* d_out, int out_size)
{
    const float* emb   = (const float*)d_in[0];
    const float* label = (const float*)d_in[1];
    const int*   did   = (const int*)d_in[2];
    float*       out   = (float*)d_out;

    // executes immediately (not a stream op); idempotent, legal during capture
    cudaFuncSetAttribute(k_gemm, cudaFuncAttributeMaxDynamicSharedMemorySize, SM_TOTAL);

    k_zero<<<(N_DOC * DIM + 255) / 256, 256>>>();
    k_norm_acc<<<N_Q, 128>>>(emb, label, did);
    k_scale<<<N_DOC, 128>>>();
    k_gemm<<<dim3(64, 8), 256, SM_TOTAL>>>();
    k_expand<<<N_Q / 8, 256>>>(did, out);
}

// round 7
// speedup vs baseline: 1.7369x; 1.0100x over previous
#include <cuda_runtime.h>
#include <cuda_bf16.h>
#include <cstdint>

#define N_Q   8192
#define DIM   384
#define N_DOC 1024
#define KSTORE 768          // [hi | lo] per row
#define NTERMS_ITERS 18     // 3 terms x 6 chunks of 64

// ---------------- scratch (static device globals; no allocation) -------------
__device__ float          g_C[(size_t)N_DOC * DIM];
__device__ float          g_den[N_DOC];
__device__ __nv_bfloat16  g_A2[(size_t)N_Q  * KSTORE];   // 12.6 MB
__device__ __nv_bfloat16  g_B2[(size_t)N_DOC * KSTORE];  //  1.6 MB
__device__ float          g_G[(size_t)N_Q * N_DOC];      // 33.5 MB

// chunk index (in units of 64 k's) for the 3-term hi/lo product:
// term1: Ah*Bh, term2: Ah*Bl, term3: Al*Bh   (lo*lo dropped, ~4e-6 rel)
__constant__ int A_CHUNK[NTERMS_ITERS] = {0,1,2,3,4,5, 0,1,2,3,4,5, 6,7,8,9,10,11};
__constant__ int B_CHUNK[NTERMS_ITERS] = {0,1,2,3,4,5, 6,7,8,9,10,11, 0,1,2,3,4,5};

// ---------------- helpers -----------------------------------------------------
__device__ __forceinline__ uint32_t smem_u32(const void* p) {
    uint32_t a;
    asm("{ .reg .u64 t; cvta.to.shared.u64 t, %1; cvt.u32.u64 %0, t; }" : "=r"(a) : "l"(p));
    return a;
}
__device__ __forceinline__ void bf_split(float x, __nv_bfloat16& h, __nv_bfloat16& l) {
    h = __float2bfloat16(x);
    l = __float2bfloat16(x - __bfloat162float(h));
}
__device__ __forceinline__ void cp16(uint32_t dst, const void* src) {
    asm volatile("cp.async.cg.shared.global [%0], [%1], 16;" :: "r"(dst), "l"(src));
}
__device__ __forceinline__ void cp_commit() { asm volatile("cp.async.commit_group;"); }
__device__ __forceinline__ void ldsm4(uint32_t& r0, uint32_t& r1, uint32_t& r2, uint32_t& r3,
                                      uint32_t addr) {
    asm volatile("ldmatrix.sync.aligned.m8n8.x4.shared.b16 {%0,%1,%2,%3}, [%4];"
                 : "=r"(r0), "=r"(r1), "=r"(r2), "=r"(r3) : "r"(addr));
}
__device__ __forceinline__ void mma16816(float* c, const uint32_t* a, const uint32_t* b) {
    asm volatile(
        "mma.sync.aligned.m16n8k16.row.col.f32.bf16.bf16.f32 "
        "{%0,%1,%2,%3}, {%4,%5,%6,%7}, {%8,%9}, {%0,%1,%2,%3};"
        : "+f"(c[0]), "+f"(c[1]), "+f"(c[2]), "+f"(c[3])
        : "r"(a[0]), "r"(a[1]), "r"(a[2]), "r"(a[3]), "r"(b[0]), "r"(b[1]));
}

// ---------------- kernel 0: zero the segment accumulators --------------------
__global__ void k_zero() {
    int idx = blockIdx.x * 256 + threadIdx.x;
    if (idx < N_DOC * DIM) g_C[idx] = 0.0f;
    if (idx < N_DOC)       g_den[idx] = 0.0f;
}

// ---------------- kernel 1: normalize + write A2 [hi|lo] + segment acc -------
__global__ __launch_bounds__(128) void k_norm_acc(
    const float* __restrict__ emb, const float* __restrict__ label,
    const int* __restrict__ did)
{
    int i = blockIdx.x;
    int t = threadIdx.x;
    const float* row = emb + (size_t)i * DIM;
    float v0 = row[t], v1 = row[t + 128], v2 = row[t + 256];
    float ss = v0 * v0 + v1 * v1 + v2 * v2;
    #pragma unroll
    for (int o = 16; o > 0; o >>= 1) ss += __shfl_xor_sync(0xFFFFFFFFu, ss, o);
    __shared__ float sred[4];
    if ((t & 31) == 0) sred[t >> 5] = ss;
    __syncthreads();
    float inv = rsqrtf(sred[0] + sred[1] + sred[2] + sred[3]);

    float q[3] = { v0 * inv, v1 * inv, v2 * inv };
    __nv_bfloat16* arow = g_A2 + (size_t)i * KSTORE;
    #pragma unroll
    for (int s = 0; s < 3; ++s) {
        int d = t + s * 128;
        __nv_bfloat16 h, l;
        bf_split(q[s], h, l);
        arow[d]       = h;
        arow[d + DIM] = l;
    }

    float w = label[i];
    int   j = did[i];
    float* crow = g_C + (size_t)j * DIM;
    atomicAdd(&crow[t],       w * q[0]);
    atomicAdd(&crow[t + 128], w * q[1]);
    atomicAdd(&crow[t + 256], w * q[2]);
    if (t == 0) atomicAdd(&g_den[j], w);
}

// ---------------- kernel 2: B2 = split(C/den) as [hi|lo] ----------------------
__global__ __launch_bounds__(128) void k_scale() {
    int j = blockIdx.x;
    float inv = 1.0f / g_den[j];
    const float* crow = g_C + (size_t)j * DIM;
    __nv_bfloat16* brow = g_B2 + (size_t)j * KSTORE;
    for (int d = threadIdx.x; d < DIM; d += 128) {
        float y = crow[d] * inv;
        __nv_bfloat16 h, l;
        bf_split(y, h, l);
        brow[d]       = h;
        brow[d + DIM] = l;
    }
}

// ---------------- kernel 3: HMMA GEMM  G = A2 * B2^T (3-term) -----------------
// 128x128 CTA tile, 4 warps (2x2), warp tile 64x64, BK=64 chunks via LUT,
// 3-stage cp.async pipeline, one __syncthreads per chunk.
// Rows 144B (128 data + 16 pad): (r*144)%128 = 16r%128 -> ldmatrix conflict-free.
#define BK        64
#define ROWB      144
#define STAGE_SB  (128 * ROWB)              // 18432 B per matrix per stage
#define STAGES    3
#define SM_TOTAL  (2 * STAGES * STAGE_SB)   // 110592 B

__device__ __forceinline__ void issue_stage(
    int s, int buf, int tid, uint32_t sAu, uint32_t sBu,
    const __nv_bfloat16* Abase, const __nv_bfloat16* Bbase)
{
    int ka = A_CHUNK[s] * BK;
    int kb = B_CHUNK[s] * BK;
    uint32_t ad = sAu + buf * STAGE_SB;
    uint32_t bd = sBu + buf * STAGE_SB;
    #pragma unroll
    for (int j = 0; j < 8; ++j) {
        int idx = tid + j * 128;
        int r = idx >> 3, c = idx & 7;
        cp16(ad + r * ROWB + c * 16, Abase + (size_t)r * KSTORE + ka + c * 8);
        cp16(bd + r * ROWB + c * 16, Bbase + (size_t)r * KSTORE + kb + c * 8);
    }
    cp_commit();
}

__global__ __launch_bounds__(128, 2) void k_gemm() {
    extern __shared__ __align__(128) char smem[];
    uint32_t sAu = smem_u32(smem);
    uint32_t sBu = sAu + STAGES * STAGE_SB;

    int tid  = threadIdx.x;
    int lane = tid & 31;
    int wid  = tid >> 5;
    int wm   = wid >> 1;             // 0..1 -> 64 rows
    int wn   = wid & 1;              // 0..1 -> 64 cols
    int tm = blockIdx.x;             // 0..63
    int tn = blockIdx.y;             // 0..7

    const __nv_bfloat16* Abase = g_A2 + (size_t)(tm * 128) * KSTORE;
    const __nv_bfloat16* Bbase = g_B2 + (size_t)(tn * 128) * KSTORE;

    float acc[4][8][4];
    #pragma unroll
    for (int i = 0; i < 4; i++)
        #pragma unroll
        for (int j = 0; j < 8; j++)
            #pragma unroll
            for (int v = 0; v < 4; v++) acc[i][j][v] = 0.0f;

    issue_stage(0, 0, tid, sAu, sBu, Abase, Bbase);
    issue_stage(1, 1, tid, sAu, sBu, Abase, Bbase);

    // fragment addressing
    int a_row = wm * 64 + (lane & 15);                      // + mi*16
    int a_off = (lane >> 4) * 16;
    int b_row = wn * 64 + ((lane >> 4) * 8 + (lane & 7));   // + nt2*16
    int b_off = ((lane >> 3) & 1) * 16;

    #pragma unroll 1
    for (int it = 0; it < NTERMS_ITERS; ++it) {
        int buf = it % STAGES;

        // After this wait, stage `it` is guaranteed landed. For the last two
        // iterations nothing new is issued, so drain fully (wait_group 0);
        // earlier iterations keep one group (stage it+1) in flight.
        if (it + 2 < NTERMS_ITERS)
            asm volatile("cp.async.wait_group 1;");
        else
            asm volatile("cp.async.wait_group 0;");
        __syncthreads();

        if (it + 2 < NTERMS_ITERS)
            issue_stage(it + 2, (it + 2) % STAGES, tid, sAu, sBu, Abase, Bbase);

        uint32_t sab = sAu + buf * STAGE_SB;
        uint32_t sbb = sBu + buf * STAGE_SB;

        #pragma unroll
        for (int kk = 0; kk < 4; ++kk) {
            uint32_t a[4][4];
            #pragma unroll
            for (int mi = 0; mi < 4; ++mi)
                ldsm4(a[mi][0], a[mi][1], a[mi][2], a[mi][3],
                      sab + (a_row + mi * 16) * ROWB + kk * 32 + a_off);
            uint32_t b[8][2];
            #pragma unroll
            for (int nt2 = 0; nt2 < 4; ++nt2) {
                uint32_t r0, r1, r2, r3;
                ldsm4(r0, r1, r2, r3,
                      sbb + (b_row + nt2 * 16) * ROWB + kk * 32 + b_off);
                b[nt2 * 2][0] = r0;     b[nt2 * 2][1] = r1;
                b[nt2 * 2 + 1][0] = r2; b[nt2 * 2 + 1][1] = r3;
            }
            #pragma unroll
            for (int mi = 0; mi < 4; ++mi)
                #pragma unroll
                for (int nj = 0; nj < 8; ++nj)
                    mma16816(acc[mi][nj], a[mi], b[nj]);
        }
    }

    // ---- epilogue: write 64x64 warp tile
    int rbase = tm * 128 + wm * 64 + (lane >> 2);
    int cbase = tn * 128 + wn * 64 + (lane & 3) * 2;
    #pragma unroll
    for (int mi = 0; mi < 4; ++mi) {
        #pragma unroll
        for (int nj = 0; nj < 8; ++nj) {
            int r = rbase + mi * 16;
            int c = cbase + nj * 8;
            *(float2*)(g_G + (size_t)r * N_DOC + c) =
                make_float2(acc[mi][nj][0], acc[mi][nj][1]);
            *(float2*)(g_G + (size_t)(r + 8) * N_DOC + c) =
                make_float2(acc[mi][nj][2], acc[mi][nj][3]);
        }
    }
}

// ---------------- kernel 4: theta[i,q] = G[i, did[q]] -------------------------
#define EXP_ROWS 16
__global__ __launch_bounds__(512) void k_expand(const int* __restrict__ did,
                                                float* __restrict__ out)
{
    __shared__ int   sdid[N_Q];   // 32 KB
    __shared__ float sG[N_DOC];   //  4 KB
    int t = threadIdx.x;
    for (int q = t; q < N_Q; q += 512) sdid[q] = did[q];

    int i0 = blockIdx.x * EXP_ROWS;
    for (int r = 0; r < EXP_ROWS; ++r) {
        int i = i0 + r;
        __syncthreads();
        for (int j = t; j < N_DOC; j += 512) sG[j] = g_G[(size_t)i * N_DOC + j];
        __syncthreads();

        float4* orow = (float4*)(out + (size_t)i * N_Q);
        const int4* sdid4 = (const int4*)sdid;
        #pragma unroll 4
        for (int q4 = t; q4 < N_Q / 4; q4 += 512) {
            int4 d4 = sdid4[q4];
            float4 v;
            v.x = sG[d4.x]; v.y = sG[d4.y]; v.z = sG[d4.z]; v.w = sG[d4.w];
            orow[q4] = v;
        }
    }
}

// ---------------- launch ------------------------------------------------------
extern "C" void kernel_launch(void* const* d_in, const int* in_sizes, int n_in,
                              void* d_out, int out_size)
{
    const float* emb   = (const float*)d_in[0];
    const float* label = (const float*)d_in[1];
    const int*   did   = (const int*)d_in[2];
    float*       out   = (float*)d_out;

    cudaFuncSetAttribute(k_gemm, cudaFuncAttributeMaxDynamicSharedMemorySize, SM_TOTAL);

    k_zero<<<(N_DOC * DIM + 255) / 256, 256>>>();
    k_norm_acc<<<N_Q, 128>>>(emb, label, did);
    k_scale<<<N_DOC, 128>>>();
    k_gemm<<<dim3(64, 8), 128, SM_TOTAL>>>();
    k_expand<<<N_Q / EXP_ROWS, 512>>>(did, out);
}

// round 9
// speedup vs baseline: 1.9268x; 1.1093x over previous
#include <cuda_runtime.h>
#include <cuda_bf16.h>
#include <cstdint>

#define N_Q   8192
#define DIM   384
#define N_DOC 1024
#define KSTORE 768          // [hi | lo] per row
#define NTERMS_ITERS 18     // 3 terms x 6 chunks of 64

// ---------------- scratch (static device globals; no allocation) -------------
__device__ float          g_C[(size_t)N_DOC * DIM];
__device__ float          g_den[N_DOC];
__device__ __nv_bfloat16  g_A2[(size_t)N_Q  * KSTORE];   // 12.6 MB
__device__ __nv_bfloat16  g_B2[(size_t)N_DOC * KSTORE];  //  1.6 MB
__device__ float          g_G[(size_t)N_Q * N_DOC];      // 33.5 MB

// chunk index (in units of 64 k's) for the 3-term hi/lo product:
// term1: Ah*Bh, term2: Ah*Bl, term3: Al*Bh   (lo*lo dropped, ~4e-6 rel)
__constant__ int A_CHUNK[NTERMS_ITERS] = {0,1,2,3,4,5, 0,1,2,3,4,5, 6,7,8,9,10,11};
__constant__ int B_CHUNK[NTERMS_ITERS] = {0,1,2,3,4,5, 6,7,8,9,10,11, 0,1,2,3,4,5};

// ---------------- helpers -----------------------------------------------------
__device__ __forceinline__ uint32_t smem_u32(const void* p) {
    uint32_t a;
    asm("{ .reg .u64 t; cvta.to.shared.u64 t, %1; cvt.u32.u64 %0, t; }" : "=r"(a) : "l"(p));
    return a;
}
__device__ __forceinline__ void bf_split(float x, __nv_bfloat16& h, __nv_bfloat16& l) {
    h = __float2bfloat16(x);
    l = __float2bfloat16(x - __bfloat162float(h));
}
__device__ __forceinline__ void cp16(uint32_t dst, const void* src) {
    asm volatile("cp.async.cg.shared.global [%0], [%1], 16;" :: "r"(dst), "l"(src));
}
__device__ __forceinline__ void cp_commit() { asm volatile("cp.async.commit_group;"); }
__device__ __forceinline__ void ldsm4(uint32_t& r0, uint32_t& r1, uint32_t& r2, uint32_t& r3,
                                      uint32_t addr) {
    asm volatile("ldmatrix.sync.aligned.m8n8.x4.shared.b16 {%0,%1,%2,%3}, [%4];"
                 : "=r"(r0), "=r"(r1), "=r"(r2), "=r"(r3) : "r"(addr));
}
__device__ __forceinline__ void mma16816(float* c, const uint32_t* a, const uint32_t* b) {
    asm volatile(
        "mma.sync.aligned.m16n8k16.row.col.f32.bf16.bf16.f32 "
        "{%0,%1,%2,%3}, {%4,%5,%6,%7}, {%8,%9}, {%0,%1,%2,%3};"
        : "+f"(c[0]), "+f"(c[1]), "+f"(c[2]), "+f"(c[3])
        : "r"(a[0]), "r"(a[1]), "r"(a[2]), "r"(a[3]), "r"(b[0]), "r"(b[1]));
}

// ---------------- kernel 0: zero the segment accumulators --------------------
__global__ void k_zero() {
    int idx = blockIdx.x * 256 + threadIdx.x;
    if (idx < N_DOC * DIM) g_C[idx] = 0.0f;
    if (idx < N_DOC)       g_den[idx] = 0.0f;
}

// ---------------- kernel 1: normalize + write A2 [hi|lo] + segment acc -------
__global__ __launch_bounds__(128) void k_norm_acc(
    const float* __restrict__ emb, const float* __restrict__ label,
    const int* __restrict__ did)
{
    int i = blockIdx.x;
    int t = threadIdx.x;
    const float* row = emb + (size_t)i * DIM;
    float v0 = row[t], v1 = row[t + 128], v2 = row[t + 256];
    float ss = v0 * v0 + v1 * v1 + v2 * v2;
    #pragma unroll
    for (int o = 16; o > 0; o >>= 1) ss += __shfl_xor_sync(0xFFFFFFFFu, ss, o);
    __shared__ float sred[4];
    if ((t & 31) == 0) sred[t >> 5] = ss;
    __syncthreads();
    float inv = rsqrtf(sred[0] + sred[1] + sred[2] + sred[3]);

    float q[3] = { v0 * inv, v1 * inv, v2 * inv };
    __nv_bfloat16* arow = g_A2 + (size_t)i * KSTORE;
    #pragma unroll
    for (int s = 0; s < 3; ++s) {
        int d = t + s * 128;
        __nv_bfloat16 h, l;
        bf_split(q[s], h, l);
        arow[d]       = h;
        arow[d + DIM] = l;
    }

    float w = label[i];
    int   j = did[i];
    float* crow = g_C + (size_t)j * DIM;
    atomicAdd(&crow[t],       w * q[0]);
    atomicAdd(&crow[t + 128], w * q[1]);
    atomicAdd(&crow[t + 256], w * q[2]);
    if (t == 0) atomicAdd(&g_den[j], w);
}

// ---------------- kernel 2: B2 = split(C/den) as [hi|lo] ----------------------
__global__ __launch_bounds__(128) void k_scale() {
    int j = blockIdx.x;
    float inv = 1.0f / g_den[j];
    const float* crow = g_C + (size_t)j * DIM;
    __nv_bfloat16* brow = g_B2 + (size_t)j * KSTORE;
    for (int d = threadIdx.x; d < DIM; d += 128) {
        float y = crow[d] * inv;
        __nv_bfloat16 h, l;
        bf_split(y, h, l);
        brow[d]       = h;
        brow[d + DIM] = l;
    }
}

// ---------------- kernel 3: HMMA GEMM  G = A2 * B2^T (3-term) -----------------
// 128x128 CTA tile, 4 warps (2x2), warp tile 64x64, BK=64 chunks via LUT,
// 3-stage cp.async pipeline, one __syncthreads per chunk.
// Rows 144B (128 data + 16 pad): (r*144)%128 = 16r%128 -> ldmatrix conflict-free.
#define BK        64
#define ROWB      144
#define STAGE_SB  (128 * ROWB)              // 18432 B per matrix per stage
#define STAGES    3
#define SM_TOTAL  (2 * STAGES * STAGE_SB)   // 110592 B

__device__ __forceinline__ void issue_stage(
    int s, int buf, int tid, uint32_t sAu, uint32_t sBu,
    const __nv_bfloat16* Abase, const __nv_bfloat16* Bbase)
{
    int ka = A_CHUNK[s] * BK;
    int kb = B_CHUNK[s] * BK;
    uint32_t ad = sAu + buf * STAGE_SB;
    uint32_t bd = sBu + buf * STAGE_SB;
    #pragma unroll
    for (int j = 0; j < 8; ++j) {
        int idx = tid + j * 128;
        int r = idx >> 3, c = idx & 7;
        cp16(ad + r * ROWB + c * 16, Abase + (size_t)r * KSTORE + ka + c * 8);
        cp16(bd + r * ROWB + c * 16, Bbase + (size_t)r * KSTORE + kb + c * 8);
    }
    cp_commit();
}

__global__ __launch_bounds__(128, 2) void k_gemm() {
    extern __shared__ __align__(128) char smem[];
    uint32_t sAu = smem_u32(smem);
    uint32_t sBu = sAu + STAGES * STAGE_SB;

    int tid  = threadIdx.x;
    int lane = tid & 31;
    int wid  = tid >> 5;
    int wm   = wid >> 1;             // 0..1 -> 64 rows
    int wn   = wid & 1;              // 0..1 -> 64 cols
    int tm = blockIdx.x;             // 0..63
    int tn = blockIdx.y;             // 0..7

    const __nv_bfloat16* Abase = g_A2 + (size_t)(tm * 128) * KSTORE;
    const __nv_bfloat16* Bbase = g_B2 + (size_t)(tn * 128) * KSTORE;

    float acc[4][8][4];
    #pragma unroll
    for (int i = 0; i < 4; i++)
        #pragma unroll
        for (int j = 0; j < 8; j++)
            #pragma unroll
            for (int v = 0; v < 4; v++) acc[i][j][v] = 0.0f;

    issue_stage(0, 0, tid, sAu, sBu, Abase, Bbase);
    issue_stage(1, 1, tid, sAu, sBu, Abase, Bbase);

    // fragment addressing
    int a_row = wm * 64 + (lane & 15);                      // + mi*16
    int a_off = (lane >> 4) * 16;
    int b_row = wn * 64 + ((lane >> 4) * 8 + (lane & 7));   // + nt2*16
    int b_off = ((lane >> 3) & 1) * 16;

    #pragma unroll 1
    for (int it = 0; it < NTERMS_ITERS; ++it) {
        int buf = it % STAGES;

        // After this wait, stage `it` is guaranteed landed. For the last two
        // iterations nothing new is issued, so drain fully (wait_group 0);
        // earlier iterations keep one group (stage it+1) in flight.
        if (it + 2 < NTERMS_ITERS)
            asm volatile("cp.async.wait_group 1;");
        else
            asm volatile("cp.async.wait_group 0;");
        __syncthreads();

        if (it + 2 < NTERMS_ITERS)
            issue_stage(it + 2, (it + 2) % STAGES, tid, sAu, sBu, Abase, Bbase);

        uint32_t sab = sAu + buf * STAGE_SB;
        uint32_t sbb = sBu + buf * STAGE_SB;

        #pragma unroll
        for (int kk = 0; kk < 4; ++kk) {
            uint32_t a[4][4];
            #pragma unroll
            for (int mi = 0; mi < 4; ++mi)
                ldsm4(a[mi][0], a[mi][1], a[mi][2], a[mi][3],
                      sab + (a_row + mi * 16) * ROWB + kk * 32 + a_off);
            uint32_t b[8][2];
            #pragma unroll
            for (int nt2 = 0; nt2 < 4; ++nt2) {
                uint32_t r0, r1, r2, r3;
                ldsm4(r0, r1, r2, r3,
                      sbb + (b_row + nt2 * 16) * ROWB + kk * 32 + b_off);
                b[nt2 * 2][0] = r0;     b[nt2 * 2][1] = r1;
                b[nt2 * 2 + 1][0] = r2; b[nt2 * 2 + 1][1] = r3;
            }
            #pragma unroll
            for (int mi = 0; mi < 4; ++mi)
                #pragma unroll
                for (int nj = 0; nj < 8; ++nj)
                    mma16816(acc[mi][nj], a[mi], b[nj]);
        }
    }

    // ---- epilogue: write 64x64 warp tile
    int rbase = tm * 128 + wm * 64 + (lane >> 2);
    int cbase = tn * 128 + wn * 64 + (lane & 3) * 2;
    #pragma unroll
    for (int mi = 0; mi < 4; ++mi) {
        #pragma unroll
        for (int nj = 0; nj < 8; ++nj) {
            int r = rbase + mi * 16;
            int c = cbase + nj * 8;
            *(float2*)(g_G + (size_t)r * N_DOC + c) =
                make_float2(acc[mi][nj][0], acc[mi][nj][1]);
            *(float2*)(g_G + (size_t)(r + 8) * N_DOC + c) =
                make_float2(acc[mi][nj][2], acc[mi][nj][3]);
        }
    }
}

// ---------------- kernel 4: theta[i,q] = G[i, did[q]] — 4-row packed gather ---
// sG4[j] packs G[i0..i0+3][j] as float4: one LDS.128 gather serves 4 output rows.
#define EXP_ROWS 16      // 4 groups of 4 rows per block
__global__ __launch_bounds__(512) void k_expand(const int* __restrict__ did,
                                                float* __restrict__ out)
{
    __shared__ int    sdid[N_Q];    // 32 KB
    __shared__ float4 sG4[N_DOC];   // 16 KB
    int t = threadIdx.x;
    for (int q = t; q < N_Q; q += 512) sdid[q] = did[q];

    int i00 = blockIdx.x * EXP_ROWS;
    #pragma unroll 1
    for (int g = 0; g < EXP_ROWS / 4; ++g) {
        int i0 = i00 + g * 4;
        __syncthreads();   // guards sdid (g==0) and sG4 reuse (g>0)
        for (int j = t; j < N_DOC; j += 512) {
            sG4[j] = make_float4(g_G[(size_t)(i0 + 0) * N_DOC + j],
                                 g_G[(size_t)(i0 + 1) * N_DOC + j],
                                 g_G[(size_t)(i0 + 2) * N_DOC + j],
                                 g_G[(size_t)(i0 + 3) * N_DOC + j]);
        }
        __syncthreads();

        const int4* sdid4 = (const int4*)sdid;
        float* o0 = out + (size_t)(i0 + 0) * N_Q;
        float* o1 = out + (size_t)(i0 + 1) * N_Q;
        float* o2 = out + (size_t)(i0 + 2) * N_Q;
        float* o3 = out + (size_t)(i0 + 3) * N_Q;
        #pragma unroll 2
        for (int q4 = t; q4 < N_Q / 4; q4 += 512) {
            int4 d4 = sdid4[q4];
            float4 f0 = sG4[d4.x];
            float4 f1 = sG4[d4.y];
            float4 f2 = sG4[d4.z];
            float4 f3 = sG4[d4.w];
            ((float4*)o0)[q4] = make_float4(f0.x, f1.x, f2.x, f3.x);
            ((float4*)o1)[q4] = make_float4(f0.y, f1.y, f2.y, f3.y);
            ((float4*)o2)[q4] = make_float4(f0.z, f1.z, f2.z, f3.z);
            ((float4*)o3)[q4] = make_float4(f0.w, f1.w, f2.w, f3.w);
        }
    }
}

// ---------------- launch ------------------------------------------------------
extern "C" void kernel_launch(void* const* d_in, const int* in_sizes, int n_in,
                              void* d_out, int out_size)
{
    const float* emb   = (const float*)d_in[0];
    const float* label = (const float*)d_in[1];
    const int*   did   = (const int*)d_in[2];
    float*       out   = (float*)d_out;

    cudaFuncSetAttribute(k_gemm, cudaFuncAttributeMaxDynamicSharedMemorySize, SM_TOTAL);

    k_zero<<<(N_DOC * DIM + 255) / 256, 256>>>();
    k_norm_acc<<<N_Q, 128>>>(emb, label, did);
    k_scale<<<N_DOC, 128>>>();
    k_gemm<<<dim3(64, 8), 128, SM_TOTAL>>>();
    k_expand<<<N_Q / EXP_ROWS, 512>>>(did, out);
}

// round 10
// speedup vs baseline: 2.2023x; 1.1430x over previous
#include <cuda_runtime.h>
#include <cuda_fp16.h>
#include <cstdint>

#define N_Q   8192
#define DIM   384
#define N_DOC 1024
#define KST_A 384           // A: fp16 hi only
#define KST_B 768           // B: [hi | lo] fp16
#define NTERMS_ITERS 12     // 2 terms x 6 chunks of 64

// ---------------- scratch (static device globals; no allocation) -------------
__device__ float   g_C[(size_t)N_DOC * DIM];
__device__ float   g_den[N_DOC];
__device__ __half  g_A2[(size_t)N_Q  * KST_A];   // 6.3 MB
__device__ __half  g_B2[(size_t)N_DOC * KST_B];  // 1.6 MB
__device__ float   g_G[(size_t)N_Q * N_DOC];     // 33.5 MB

// chunk LUT (units of 64 k's): term1 = Ah*Bh, term2 = Ah*Bl  (A*lo dropped,
// error ~ Al*B ~ 2e-4 rel, under the 1e-3 gate)
__constant__ int A_CHUNK[NTERMS_ITERS] = {0,1,2,3,4,5, 0,1,2,3,4,5};
__constant__ int B_CHUNK[NTERMS_ITERS] = {0,1,2,3,4,5, 6,7,8,9,10,11};

// ---------------- helpers -----------------------------------------------------
__device__ __forceinline__ uint32_t smem_u32(const void* p) {
    uint32_t a;
    asm("{ .reg .u64 t; cvta.to.shared.u64 t, %1; cvt.u32.u64 %0, t; }" : "=r"(a) : "l"(p));
    return a;
}
__device__ __forceinline__ void h_split(float x, __half& h, __half& l) {
    h = __float2half(x);
    l = __float2half(x - __half2float(h));
}
__device__ __forceinline__ void cp16(uint32_t dst, const void* src) {
    asm volatile("cp.async.cg.shared.global [%0], [%1], 16;" :: "r"(dst), "l"(src));
}
__device__ __forceinline__ void cp_commit() { asm volatile("cp.async.commit_group;"); }
__device__ __forceinline__ void ldsm4(uint32_t& r0, uint32_t& r1, uint32_t& r2, uint32_t& r3,
                                      uint32_t addr) {
    asm volatile("ldmatrix.sync.aligned.m8n8.x4.shared.b16 {%0,%1,%2,%3}, [%4];"
                 : "=r"(r0), "=r"(r1), "=r"(r2), "=r"(r3) : "r"(addr));
}
__device__ __forceinline__ void mma16816(float* c, const uint32_t* a, const uint32_t* b) {
    asm volatile(
        "mma.sync.aligned.m16n8k16.row.col.f32.f16.f16.f32 "
        "{%0,%1,%2,%3}, {%4,%5,%6,%7}, {%8,%9}, {%0,%1,%2,%3};"
        : "+f"(c[0]), "+f"(c[1]), "+f"(c[2]), "+f"(c[3])
        : "r"(a[0]), "r"(a[1]), "r"(a[2]), "r"(a[3]), "r"(b[0]), "r"(b[1]));
}

// ---------------- kernel 0: zero the segment accumulators --------------------
__global__ void k_zero() {
    int idx = blockIdx.x * 256 + threadIdx.x;
    if (idx < N_DOC * DIM) g_C[idx] = 0.0f;
    if (idx < N_DOC)       g_den[idx] = 0.0f;
}

// ---------------- kernel 1: normalize + write A2 (fp16 hi) + segment acc -----
__global__ __launch_bounds__(128) void k_norm_acc(
    const float* __restrict__ emb, const float* __restrict__ label,
    const int* __restrict__ did)
{
    int i = blockIdx.x;
    int t = threadIdx.x;
    const float* row = emb + (size_t)i * DIM;
    float v0 = row[t], v1 = row[t + 128], v2 = row[t + 256];
    float ss = v0 * v0 + v1 * v1 + v2 * v2;
    #pragma unroll
    for (int o = 16; o > 0; o >>= 1) ss += __shfl_xor_sync(0xFFFFFFFFu, ss, o);
    __shared__ float sred[4];
    if ((t & 31) == 0) sred[t >> 5] = ss;
    __syncthreads();
    float inv = rsqrtf(sred[0] + sred[1] + sred[2] + sred[3]);

    float q[3] = { v0 * inv, v1 * inv, v2 * inv };
    __half* arow = g_A2 + (size_t)i * KST_A;
    #pragma unroll
    for (int s = 0; s < 3; ++s)
        arow[t + s * 128] = __float2half(q[s]);

    float w = label[i];
    int   j = did[i];
    float* crow = g_C + (size_t)j * DIM;
    atomicAdd(&crow[t],       w * q[0]);
    atomicAdd(&crow[t + 128], w * q[1]);
    atomicAdd(&crow[t + 256], w * q[2]);
    if (t == 0) atomicAdd(&g_den[j], w);
}

// ---------------- kernel 2: B2 = split(C/den) as fp16 [hi|lo] -----------------
__global__ __launch_bounds__(128) void k_scale() {
    int j = blockIdx.x;
    float inv = 1.0f / g_den[j];
    const float* crow = g_C + (size_t)j * DIM;
    __half* brow = g_B2 + (size_t)j * KST_B;
    for (int d = threadIdx.x; d < DIM; d += 128) {
        float y = crow[d] * inv;
        __half h, l;
        h_split(y, h, l);
        brow[d]       = h;
        brow[d + DIM] = l;
    }
}

// ---------------- kernel 3: HMMA GEMM  G = A2 * B2^T (2-term fp16) ------------
// 128x128 CTA tile, 4 warps (2x2), warp tile 64x64, BK=64 chunks via LUT,
// 3-stage cp.async pipeline, one __syncthreads per chunk.
// Rows 144B (128 data + 16 pad): (r*144)%128 = 16r%128 -> ldmatrix conflict-free.
#define BK        64
#define ROWB      144
#define STAGE_SB  (128 * ROWB)              // 18432 B per matrix per stage
#define STAGES    3
#define SM_TOTAL  (2 * STAGES * STAGE_SB)   // 110592 B

__device__ __forceinline__ void issue_stage(
    int s, int buf, int tid, uint32_t sAu, uint32_t sBu,
    const __half* Abase, const __half* Bbase)
{
    int ka = A_CHUNK[s] * BK;
    int kb = B_CHUNK[s] * BK;
    uint32_t ad = sAu + buf * STAGE_SB;
    uint32_t bd = sBu + buf * STAGE_SB;
    #pragma unroll
    for (int j = 0; j < 8; ++j) {
        int idx = tid + j * 128;
        int r = idx >> 3, c = idx & 7;
        cp16(ad + r * ROWB + c * 16, Abase + (size_t)r * KST_A + ka + c * 8);
        cp16(bd + r * ROWB + c * 16, Bbase + (size_t)r * KST_B + kb + c * 8);
    }
    cp_commit();
}

__global__ __launch_bounds__(128, 2) void k_gemm() {
    extern __shared__ __align__(128) char smem[];
    uint32_t sAu = smem_u32(smem);
    uint32_t sBu = sAu + STAGES * STAGE_SB;

    int tid  = threadIdx.x;
    int lane = tid & 31;
    int wid  = tid >> 5;
    int wm   = wid >> 1;             // 0..1 -> 64 rows
    int wn   = wid & 1;              // 0..1 -> 64 cols
    int tm = blockIdx.x;             // 0..63
    int tn = blockIdx.y;             // 0..7

    const __half* Abase = g_A2 + (size_t)(tm * 128) * KST_A;
    const __half* Bbase = g_B2 + (size_t)(tn * 128) * KST_B;

    float acc[4][8][4];
    #pragma unroll
    for (int i = 0; i < 4; i++)
        #pragma unroll
        for (int j = 0; j < 8; j++)
            #pragma unroll
            for (int v = 0; v < 4; v++) acc[i][j][v] = 0.0f;

    issue_stage(0, 0, tid, sAu, sBu, Abase, Bbase);
    issue_stage(1, 1, tid, sAu, sBu, Abase, Bbase);

    // fragment addressing
    int a_row = wm * 64 + (lane & 15);                      // + mi*16
    int a_off = (lane >> 4) * 16;
    int b_row = wn * 64 + ((lane >> 4) * 8 + (lane & 7));   // + nt2*16
    int b_off = ((lane >> 3) & 1) * 16;

    #pragma unroll 1
    for (int it = 0; it < NTERMS_ITERS; ++it) {
        int buf = it % STAGES;

        // After this wait, stage `it` is guaranteed landed. For the last two
        // iterations nothing new is issued, so drain fully (wait_group 0);
        // earlier iterations keep one group (stage it+1) in flight.
        if (it + 2 < NTERMS_ITERS)
            asm volatile("cp.async.wait_group 1;");
        else
            asm volatile("cp.async.wait_group 0;");
        __syncthreads();

        if (it + 2 < NTERMS_ITERS)
            issue_stage(it + 2, (it + 2) % STAGES, tid, sAu, sBu, Abase, Bbase);

        uint32_t sab = sAu + buf * STAGE_SB;
        uint32_t sbb = sBu + buf * STAGE_SB;

        #pragma unroll
        for (int kk = 0; kk < 4; ++kk) {
            uint32_t a[4][4];
            #pragma unroll
            for (int mi = 0; mi < 4; ++mi)
                ldsm4(a[mi][0], a[mi][1], a[mi][2], a[mi][3],
                      sab + (a_row + mi * 16) * ROWB + kk * 32 + a_off);
            uint32_t b[8][2];
            #pragma unroll
            for (int nt2 = 0; nt2 < 4; ++nt2) {
                uint32_t r0, r1, r2, r3;
                ldsm4(r0, r1, r2, r3,
                      sbb + (b_row + nt2 * 16) * ROWB + kk * 32 + b_off);
                b[nt2 * 2][0] = r0;     b[nt2 * 2][1] = r1;
                b[nt2 * 2 + 1][0] = r2; b[nt2 * 2 + 1][1] = r3;
            }
            #pragma unroll
            for (int mi = 0; mi < 4; ++mi)
                #pragma unroll
                for (int nj = 0; nj < 8; ++nj)
                    mma16816(acc[mi][nj], a[mi], b[nj]);
        }
    }

    // ---- epilogue: write 64x64 warp tile
    int rbase = tm * 128 + wm * 64 + (lane >> 2);
    int cbase = tn * 128 + wn * 64 + (lane & 3) * 2;
    #pragma unroll
    for (int mi = 0; mi < 4; ++mi) {
        #pragma unroll
        for (int nj = 0; nj < 8; ++nj) {
            int r = rbase + mi * 16;
            int c = cbase + nj * 8;
            *(float2*)(g_G + (size_t)r * N_DOC + c) =
                make_float2(acc[mi][nj][0], acc[mi][nj][1]);
            *(float2*)(g_G + (size_t)(r + 8) * N_DOC + c) =
                make_float2(acc[mi][nj][2], acc[mi][nj][3]);
        }
    }
}

// ---------------- kernel 4: theta[i,q] = G[i, did[q]] — 4-row packed gather ---
// sG4[j] packs G[i0..i0+3][j] as float4: one LDS.128 gather serves 4 output rows.
#define EXP_ROWS 16      // 4 groups of 4 rows per block
__global__ __launch_bounds__(512) void k_expand(const int* __restrict__ did,
                                                float* __restrict__ out)
{
    __shared__ int    sdid[N_Q];    // 32 KB
    __shared__ float4 sG4[N_DOC];   // 16 KB
    int t = threadIdx.x;
    for (int q = t; q < N_Q; q += 512) sdid[q] = did[q];

    int i00 = blockIdx.x * EXP_ROWS;
    #pragma unroll 1
    for (int g = 0; g < EXP_ROWS / 4; ++g) {
        int i0 = i00 + g * 4;
        __syncthreads();   // guards sdid (g==0) and sG4 reuse (g>0)
        for (int j = t; j < N_DOC; j += 512) {
            sG4[j] = make_float4(g_G[(size_t)(i0 + 0) * N_DOC + j],
                                 g_G[(size_t)(i0 + 1) * N_DOC + j],
                                 g_G[(size_t)(i0 + 2) * N_DOC + j],
                                 g_G[(size_t)(i0 + 3) * N_DOC + j]);
        }
        __syncthreads();

        const int4* sdid4 = (const int4*)sdid;
        float* o0 = out + (size_t)(i0 + 0) * N_Q;
        float* o1 = out + (size_t)(i0 + 1) * N_Q;
        float* o2 = out + (size_t)(i0 + 2) * N_Q;
        float* o3 = out + (size_t)(i0 + 3) * N_Q;
        #pragma unroll 2
        for (int q4 = t; q4 < N_Q / 4; q4 += 512) {
            int4 d4 = sdid4[q4];
            float4 f0 = sG4[d4.x];
            float4 f1 = sG4[d4.y];
            float4 f2 = sG4[d4.z];
            float4 f3 = sG4[d4.w];
            ((float4*)o0)[q4] = make_float4(f0.x, f1.x, f2.x, f3.x);
            ((float4*)o1)[q4] = make_float4(f0.y, f1.y, f2.y, f3.y);
            ((float4*)o2)[q4] = make_float4(f0.z, f1.z, f2.z, f3.z);
            ((float4*)o3)[q4] = make_float4(f0.w, f1.w, f2.w, f3.w);
        }
    }
}

// ---------------- launch ------------------------------------------------------
extern "C" void kernel_launch(void* const* d_in, const int* in_sizes, int n_in,
                              void* d_out, int out_size)
{
    const float* emb   = (const float*)d_in[0];
    const float* label = (const float*)d_in[1];
    const int*   did   = (const int*)d_in[2];
    float*       out   = (float*)d_out;

    cudaFuncSetAttribute(k_gemm, cudaFuncAttributeMaxDynamicSharedMemorySize, SM_TOTAL);

    k_zero<<<(N_DOC * DIM + 255) / 256, 256>>>();
    k_norm_acc<<<N_Q, 128>>>(emb, label, did);
    k_scale<<<N_DOC, 128>>>();
    k_gemm<<<dim3(64, 8), 128, SM_TOTAL>>>();
    k_expand<<<N_Q / EXP_ROWS, 512>>>(did, out);
}

// round 11
// speedup vs baseline: 2.6569x; 1.2064x over previous
#include <cuda_runtime.h>
#include <cuda_fp16.h>
#include <cstdint>

#define N_Q   8192
#define DIM   384
#define N_DOC 1024
#define KST   384           // fp16 hi only, both operands
#define K_ITERS 6           // 6 chunks of 64

// ---------------- scratch (static device globals; no allocation) -------------
__device__ float   g_C[(size_t)N_DOC * DIM];
__device__ float   g_den[N_DOC];
__device__ __half  g_A2[(size_t)N_Q  * KST];    // 6.3 MB
__device__ __half  g_B2[(size_t)N_DOC * KST];   // 0.8 MB
__device__ float   g_G[(size_t)N_Q * N_DOC];    // 33.5 MB

// ---------------- helpers -----------------------------------------------------
__device__ __forceinline__ uint32_t smem_u32(const void* p) {
    uint32_t a;
    asm("{ .reg .u64 t; cvta.to.shared.u64 t, %1; cvt.u32.u64 %0, t; }" : "=r"(a) : "l"(p));
    return a;
}
__device__ __forceinline__ void cp16(uint32_t dst, const void* src) {
    asm volatile("cp.async.cg.shared.global [%0], [%1], 16;" :: "r"(dst), "l"(src));
}
__device__ __forceinline__ void cp_commit() { asm volatile("cp.async.commit_group;"); }
__device__ __forceinline__ void ldsm4(uint32_t& r0, uint32_t& r1, uint32_t& r2, uint32_t& r3,
                                      uint32_t addr) {
    asm volatile("ldmatrix.sync.aligned.m8n8.x4.shared.b16 {%0,%1,%2,%3}, [%4];"
                 : "=r"(r0), "=r"(r1), "=r"(r2), "=r"(r3) : "r"(addr));
}
__device__ __forceinline__ void mma16816(float* c, const uint32_t* a, const uint32_t* b) {
    asm volatile(
        "mma.sync.aligned.m16n8k16.row.col.f32.f16.f16.f32 "
        "{%0,%1,%2,%3}, {%4,%5,%6,%7}, {%8,%9}, {%0,%1,%2,%3};"
        : "+f"(c[0]), "+f"(c[1]), "+f"(c[2]), "+f"(c[3])
        : "r"(a[0]), "r"(a[1]), "r"(a[2]), "r"(a[3]), "r"(b[0]), "r"(b[1]));
}

// ---------------- kernel 0: zero the segment accumulators --------------------
__global__ void k_zero() {
    int idx = blockIdx.x * 256 + threadIdx.x;
    if (idx < N_DOC * DIM) g_C[idx] = 0.0f;
    if (idx < N_DOC)       g_den[idx] = 0.0f;
}

// ---------------- kernel 1: normalize + write A2 (fp16) + segment acc --------
__global__ __launch_bounds__(128) void k_norm_acc(
    const float* __restrict__ emb, const float* __restrict__ label,
    const int* __restrict__ did)
{
    int i = blockIdx.x;
    int t = threadIdx.x;
    const float* row = emb + (size_t)i * DIM;
    float v0 = row[t], v1 = row[t + 128], v2 = row[t + 256];
    float ss = v0 * v0 + v1 * v1 + v2 * v2;
    #pragma unroll
    for (int o = 16; o > 0; o >>= 1) ss += __shfl_xor_sync(0xFFFFFFFFu, ss, o);
    __shared__ float sred[4];
    if ((t & 31) == 0) sred[t >> 5] = ss;
    __syncthreads();
    float inv = rsqrtf(sred[0] + sred[1] + sred[2] + sred[3]);

    float q[3] = { v0 * inv, v1 * inv, v2 * inv };
    __half* arow = g_A2 + (size_t)i * KST;
    #pragma unroll
    for (int s = 0; s < 3; ++s)
        arow[t + s * 128] = __float2half(q[s]);

    float w = label[i];
    int   j = did[i];
    float* crow = g_C + (size_t)j * DIM;
    atomicAdd(&crow[t],       w * q[0]);
    atomicAdd(&crow[t + 128], w * q[1]);
    atomicAdd(&crow[t + 256], w * q[2]);
    if (t == 0) atomicAdd(&g_den[j], w);
}

// ---------------- kernel 2: B2 = fp16(C/den) ----------------------------------
__global__ __launch_bounds__(128) void k_scale() {
    int j = blockIdx.x;
    float inv = 1.0f / g_den[j];
    const float* crow = g_C + (size_t)j * DIM;
    __half* brow = g_B2 + (size_t)j * KST;
    for (int d = threadIdx.x; d < DIM; d += 128)
        brow[d] = __float2half(crow[d] * inv);
}

// ---------------- kernel 3: HMMA GEMM  G = A2 * B2^T (pure fp16) --------------
// 128x128 CTA tile, 4 warps (2x2), warp tile 64x64, BK=64,
// 3-stage cp.async pipeline, one __syncthreads per chunk.
// Rows 144B (128 data + 16 pad): (r*144)%128 = 16r%128 -> ldmatrix conflict-free.
#define BK        64
#define ROWB      144
#define STAGE_SB  (128 * ROWB)              // 18432 B per matrix per stage
#define STAGES    3
#define SM_TOTAL  (2 * STAGES * STAGE_SB)   // 110592 B

__device__ __forceinline__ void issue_stage(
    int s, int buf, int tid, uint32_t sAu, uint32_t sBu,
    const __half* Abase, const __half* Bbase)
{
    int k0 = s * BK;
    uint32_t ad = sAu + buf * STAGE_SB;
    uint32_t bd = sBu + buf * STAGE_SB;
    #pragma unroll
    for (int j = 0; j < 8; ++j) {
        int idx = tid + j * 128;
        int r = idx >> 3, c = idx & 7;
        cp16(ad + r * ROWB + c * 16, Abase + (size_t)r * KST + k0 + c * 8);
        cp16(bd + r * ROWB + c * 16, Bbase + (size_t)r * KST + k0 + c * 8);
    }
    cp_commit();
}

__global__ __launch_bounds__(128, 2) void k_gemm() {
    extern __shared__ __align__(128) char smem[];
    uint32_t sAu = smem_u32(smem);
    uint32_t sBu = sAu + STAGES * STAGE_SB;

    int tid  = threadIdx.x;
    int lane = tid & 31;
    int wid  = tid >> 5;
    int wm   = wid >> 1;             // 0..1 -> 64 rows
    int wn   = wid & 1;              // 0..1 -> 64 cols
    int tm = blockIdx.x;             // 0..63
    int tn = blockIdx.y;             // 0..7

    const __half* Abase = g_A2 + (size_t)(tm * 128) * KST;
    const __half* Bbase = g_B2 + (size_t)(tn * 128) * KST;

    float acc[4][8][4];
    #pragma unroll
    for (int i = 0; i < 4; i++)
        #pragma unroll
        for (int j = 0; j < 8; j++)
            #pragma unroll
            for (int v = 0; v < 4; v++) acc[i][j][v] = 0.0f;

    issue_stage(0, 0, tid, sAu, sBu, Abase, Bbase);
    issue_stage(1, 1, tid, sAu, sBu, Abase, Bbase);

    // fragment addressing
    int a_row = wm * 64 + (lane & 15);                      // + mi*16
    int a_off = (lane >> 4) * 16;
    int b_row = wn * 64 + ((lane >> 4) * 8 + (lane & 7));   // + nt2*16
    int b_off = ((lane >> 3) & 1) * 16;

    #pragma unroll 1
    for (int it = 0; it < K_ITERS; ++it) {
        int buf = it % STAGES;

        // After this wait, stage `it` is guaranteed landed. For the last two
        // iterations nothing new is issued, so drain fully (wait_group 0);
        // earlier iterations keep one group (stage it+1) in flight.
        if (it + 2 < K_ITERS)
            asm volatile("cp.async.wait_group 1;");
        else
            asm volatile("cp.async.wait_group 0;");
        __syncthreads();

        if (it + 2 < K_ITERS)
            issue_stage(it + 2, (it + 2) % STAGES, tid, sAu, sBu, Abase, Bbase);

        uint32_t sab = sAu + buf * STAGE_SB;
        uint32_t sbb = sBu + buf * STAGE_SB;

        #pragma unroll
        for (int kk = 0; kk < 4; ++kk) {
            uint32_t a[4][4];
            #pragma unroll
            for (int mi = 0; mi < 4; ++mi)
                ldsm4(a[mi][0], a[mi][1], a[mi][2], a[mi][3],
                      sab + (a_row + mi * 16) * ROWB + kk * 32 + a_off);
            uint32_t b[8][2];
            #pragma unroll
            for (int nt2 = 0; nt2 < 4; ++nt2) {
                uint32_t r0, r1, r2, r3;
                ldsm4(r0, r1, r2, r3,
                      sbb + (b_row + nt2 * 16) * ROWB + kk * 32 + b_off);
                b[nt2 * 2][0] = r0;     b[nt2 * 2][1] = r1;
                b[nt2 * 2 + 1][0] = r2; b[nt2 * 2 + 1][1] = r3;
            }
            #pragma unroll
            for (int mi = 0; mi < 4; ++mi)
                #pragma unroll
                for (int nj = 0; nj < 8; ++nj)
                    mma16816(acc[mi][nj], a[mi], b[nj]);
        }
    }

    // ---- epilogue: write 64x64 warp tile
    int rbase = tm * 128 + wm * 64 + (lane >> 2);
    int cbase = tn * 128 + wn * 64 + (lane & 3) * 2;
    #pragma unroll
    for (int mi = 0; mi < 4; ++mi) {
        #pragma unroll
        for (int nj = 0; nj < 8; ++nj) {
            int r = rbase + mi * 16;
            int c = cbase + nj * 8;
            *(float2*)(g_G + (size_t)r * N_DOC + c) =
                make_float2(acc[mi][nj][0], acc[mi][nj][1]);
            *(float2*)(g_G + (size_t)(r + 8) * N_DOC + c) =
                make_float2(acc[mi][nj][2], acc[mi][nj][3]);
        }
    }
}

// ---------------- kernel 4: theta[i,q] = G[i, did[q]] — 4-row packed gather ---
// sG4[j] packs G[i0..i0+3][j] as float4: one LDS.128 gather serves 4 output rows.
#define EXP_ROWS 16      // 4 groups of 4 rows per block
__global__ __launch_bounds__(512) void k_expand(const int* __restrict__ did,
                                                float* __restrict__ out)
{
    __shared__ int    sdid[N_Q];    // 32 KB
    __shared__ float4 sG4[N_DOC];   // 16 KB
    int t = threadIdx.x;
    for (int q = t; q < N_Q; q += 512) sdid[q] = did[q];

    int i00 = blockIdx.x * EXP_ROWS;
    #pragma unroll 1
    for (int g = 0; g < EXP_ROWS / 4; ++g) {
        int i0 = i00 + g * 4;
        __syncthreads();   // guards sdid (g==0) and sG4 reuse (g>0)
        for (int j = t; j < N_DOC; j += 512) {
            sG4[j] = make_float4(g_G[(size_t)(i0 + 0) * N_DOC + j],
                                 g_G[(size_t)(i0 + 1) * N_DOC + j],
                                 g_G[(size_t)(i0 + 2) * N_DOC + j],
                                 g_G[(size_t)(i0 + 3) * N_DOC + j]);
        }
        __syncthreads();

        const int4* sdid4 = (const int4*)sdid;
        float* o0 = out + (size_t)(i0 + 0) * N_Q;
        float* o1 = out + (size_t)(i0 + 1) * N_Q;
        float* o2 = out + (size_t)(i0 + 2) * N_Q;
        float* o3 = out + (size_t)(i0 + 3) * N_Q;
        #pragma unroll 2
        for (int q4 = t; q4 < N_Q / 4; q4 += 512) {
            int4 d4 = sdid4[q4];
            float4 f0 = sG4[d4.x];
            float4 f1 = sG4[d4.y];
            float4 f2 = sG4[d4.z];
            float4 f3 = sG4[d4.w];
            ((float4*)o0)[q4] = make_float4(f0.x, f1.x, f2.x, f3.x);
            ((float4*)o1)[q4] = make_float4(f0.y, f1.y, f2.y, f3.y);
            ((float4*)o2)[q4] = make_float4(f0.z, f1.z, f2.z, f3.z);
            ((float4*)o3)[q4] = make_float4(f0.w, f1.w, f2.w, f3.w);
        }
    }
}

// ---------------- launch ------------------------------------------------------
extern "C" void kernel_launch(void* const* d_in, const int* in_sizes, int n_in,
                              void* d_out, int out_size)
{
    const float* emb   = (const float*)d_in[0];
    const float* label = (const float*)d_in[1];
    const int*   did   = (const int*)d_in[2];
    float*       out   = (float*)d_out;

    cudaFuncSetAttribute(k_gemm, cudaFuncAttributeMaxDynamicSharedMemorySize, SM_TOTAL);

    k_zero<<<(N_DOC * DIM + 255) / 256, 256>>>();
    k_norm_acc<<<N_Q, 128>>>(emb, label, did);
    k_scale<<<N_DOC, 128>>>();
    k_gemm<<<dim3(64, 8), 128, SM_TOTAL>>>();
    k_expand<<<N_Q / EXP_ROWS, 512>>>(did, out);
}